// round 12
// baseline (speedup 1.0000x reference)
#include <cuda_runtime.h>
#include <cuda_bf16.h>
#include <cstdint>

#define T_STEPS 512
#define BATCH   32
#define DIM     1024
#define NS      64
#define M_TOT   (T_STEPS * BATCH)   // 16384

// ---------------------------------------------------------------------------
// Device scratch
// ---------------------------------------------------------------------------
__device__ __align__(16) float  g_proj[(size_t)M_TOT * 256];   // [m][{k,q,v,ax}x64]
__device__ __align__(16) float4 g_kk[M_TOT];
__device__ __align__(16) __nv_bfloat16 g_Wh[256 * DIM];        // rows: k,q,v,ax
__device__ __align__(16) __nv_bfloat16 g_Wl[256 * DIM];

// ---------------------------------------------------------------------------
// helpers
// ---------------------------------------------------------------------------
__device__ __forceinline__ uint32_t smem_u32(const void* p) {
    uint32_t a;
    asm("{ .reg .u64 t; cvta.to.shared.u64 t, %1; cvt.u32.u64 %0, t; }" : "=r"(a) : "l"(p));
    return a;
}
__device__ __forceinline__ uint32_t bfpack(float hi_elem, float lo_elem) {
    uint32_t r;
    asm("cvt.rn.bf16x2.f32 %0, %1, %2;" : "=r"(r) : "f"(hi_elem), "f"(lo_elem));
    return r;
}
__device__ __forceinline__ uint32_t swoff(int row, int unit) {
    return (uint32_t)(row * 64 + ((unit ^ ((row >> 1) & 3)) << 4));
}
__device__ __forceinline__ void cp16(uint32_t dst, const void* src) {
    asm volatile("cp.async.cg.shared.global [%0], [%1], 16;" :: "r"(dst), "l"(src) : "memory");
}
__device__ __forceinline__ void ldsm4(uint32_t* r, uint32_t a) {
    asm volatile("ldmatrix.sync.aligned.m8n8.x4.shared.b16 {%0,%1,%2,%3}, [%4];"
                 : "=r"(r[0]), "=r"(r[1]), "=r"(r[2]), "=r"(r[3]) : "r"(a));
}
__device__ __forceinline__ void ldsm2(uint32_t* r, uint32_t a) {
    asm volatile("ldmatrix.sync.aligned.m8n8.x2.shared.b16 {%0,%1}, [%2];"
                 : "=r"(r[0]), "=r"(r[1]) : "r"(a));
}
__device__ __forceinline__ void mma16816(float* c, const uint32_t* a, const uint32_t* b) {
    asm volatile(
        "mma.sync.aligned.m16n8k16.row.col.f32.bf16.bf16.f32 "
        "{%0,%1,%2,%3}, {%4,%5,%6,%7}, {%8,%9}, {%0,%1,%2,%3};"
        : "+f"(c[0]), "+f"(c[1]), "+f"(c[2]), "+f"(c[3])
        : "r"(a[0]), "r"(a[1]), "r"(a[2]), "r"(a[3]), "r"(b[0]), "r"(b[1]));
}

// ---------------------------------------------------------------------------
// Weight prep: split 4x[64,1024] fp32 into bf16 hi/lo, row order k,q,v,ax
// ---------------------------------------------------------------------------
__global__ __launch_bounds__(256) void prep_w(
    const float* __restrict__ Wk, const float* __restrict__ Wq,
    const float* __restrict__ Wv, const float* __restrict__ Wa)
{
    int idx = blockIdx.x * 256 + threadIdx.x;
    int r = idx >> 8, c4 = idx & 255;
    const float* W = (r < 64) ? Wk : (r < 128) ? Wq : (r < 192) ? Wv : Wa;
    float4 v = ((const float4*)(W + (size_t)(r & 63) * DIM))[c4];
    uint32_t h01 = bfpack(v.y, v.x);
    uint32_t h23 = bfpack(v.w, v.z);
    float l0 = v.x - __uint_as_float(h01 << 16);
    float l1 = v.y - __uint_as_float(h01 & 0xffff0000u);
    float l2 = v.z - __uint_as_float(h23 << 16);
    float l3 = v.w - __uint_as_float(h23 & 0xffff0000u);
    ((uint2*)g_Wh)[idx] = make_uint2(h01, h23);
    ((uint2*)g_Wl)[idx] = make_uint2(bfpack(l1, l0), bfpack(l3, l2));
}

// ---------------------------------------------------------------------------
// Tensor-core projection GEMM (mma.sync bf16x3) — unchanged (R7, passed)
// ---------------------------------------------------------------------------
#define STAGE_BYTES 49152
#define GEMM_SMEM   (2 * STAGE_BYTES)

__global__ __launch_bounds__(512) void proj_gemm_mma(const float* __restrict__ X)
{
    extern __shared__ char sm[];
    const uint32_t sb = smem_u32(sm);
    const int tid  = threadIdx.x;
    const int lane = tid & 31;
    const int wid  = tid >> 5;
    const int wm   = wid & 3;
    const int wn   = wid >> 2;
    const int m0   = blockIdx.x * 128;

    float c[2][8][4];
    #pragma unroll
    for (int i = 0; i < 2; i++)
        #pragma unroll
        for (int j = 0; j < 8; j++)
            #pragma unroll
            for (int q = 0; q < 4; q++) c[i][j][q] = 0.f;

    const int xrow = tid >> 2, xu = tid & 3;
    const int wp   = tid >> 8, wrow = tid & 255;

    auto issueW = [&](int ch, int s) {
        const __nv_bfloat16* src = (wp ? g_Wl : g_Wh) + (size_t)wrow * DIM + ch * 32;
        uint32_t dbase = sb + s * STAGE_BYTES + 16384 + wp * 16384;
        #pragma unroll
        for (int u = 0; u < 4; u++) cp16(dbase + swoff(wrow, u), src + u * 8);
        asm volatile("cp.async.commit_group;" ::: "memory");
    };
    float4 xa, xb;
    auto loadX = [&](int ch) {
        const float* p = X + (size_t)(m0 + xrow) * DIM + ch * 32 + xu * 8;
        xa = *(const float4*)p;
        xb = *(const float4*)(p + 4);
    };
    auto stsX = [&](int s) {
        uint32_t h01 = bfpack(xa.y, xa.x), h23 = bfpack(xa.w, xa.z);
        uint32_t h45 = bfpack(xb.y, xb.x), h67 = bfpack(xb.w, xb.z);
        float l0 = xa.x - __uint_as_float(h01 << 16);
        float l1 = xa.y - __uint_as_float(h01 & 0xffff0000u);
        float l2 = xa.z - __uint_as_float(h23 << 16);
        float l3 = xa.w - __uint_as_float(h23 & 0xffff0000u);
        float l4 = xb.x - __uint_as_float(h45 << 16);
        float l5 = xb.y - __uint_as_float(h45 & 0xffff0000u);
        float l6 = xb.z - __uint_as_float(h67 << 16);
        float l7 = xb.w - __uint_as_float(h67 & 0xffff0000u);
        uint32_t off = s * STAGE_BYTES + swoff(xrow, xu);
        *(uint4*)(sm + off)        = make_uint4(h01, h23, h45, h67);
        *(uint4*)(sm + off + 8192) = make_uint4(bfpack(l1, l0), bfpack(l3, l2),
                                                bfpack(l5, l4), bfpack(l7, l6));
    };

    issueW(0, 0);
    loadX(0);

    for (int ch = 0; ch < 32; ch++) {
        const int s = ch & 1;
        asm volatile("cp.async.wait_group 0;" ::: "memory");
        stsX(s);
        if (ch + 1 < 32) { issueW(ch + 1, s ^ 1); loadX(ch + 1); }
        __syncthreads();

        const uint32_t st = sb + s * STAGE_BYTES;
        #pragma unroll
        for (int kt = 0; kt < 2; kt++) {
            uint32_t ah[2][4], al[2][4];
            #pragma unroll
            for (int mt = 0; mt < 2; mt++) {
                uint32_t aoff = swoff(wm * 32 + mt * 16 + (lane & 15), kt * 2 + (lane >> 4));
                ldsm4(ah[mt], st + aoff);
                ldsm4(al[mt], st + 8192 + aoff);
            }
            #pragma unroll
            for (int nt = 0; nt < 8; nt++) {
                uint32_t boff = swoff(wn * 64 + nt * 8 + (lane & 7),
                                      kt * 2 + ((lane >> 3) & 1));
                uint32_t bh[2], bl[2];
                ldsm2(bh, st + 16384 + boff);
                ldsm2(bl, st + 32768 + boff);
                mma16816(c[0][nt], ah[0], bh);
                mma16816(c[1][nt], ah[1], bh);
                mma16816(c[0][nt], al[0], bh);
                mma16816(c[1][nt], al[1], bh);
                mma16816(c[0][nt], ah[0], bl);
                mma16816(c[1][nt], ah[1], bl);
            }
        }
        __syncthreads();
    }

    #pragma unroll
    for (int mt = 0; mt < 2; mt++) {
        #pragma unroll
        for (int nt = 0; nt < 8; nt++) {
            int m = m0 + wm * 32 + mt * 16 + (lane >> 2);
            int n = wn * 64 + nt * 8 + (lane & 3) * 2;
            *(float2*)&g_proj[(size_t)m * 256 + n]       = make_float2(c[mt][nt][0], c[mt][nt][1]);
            *(float2*)&g_proj[(size_t)(m + 8) * 256 + n] = make_float2(c[mt][nt][2], c[mt][nt][3]);
        }
    }
}

// ---------------------------------------------------------------------------
// kk kernel: g_kk[t][b] = {k_t·k_{t+1}, k_t·k_{t+2}, k_t·k_{t+3}, 0}
// ---------------------------------------------------------------------------
__global__ __launch_bounds__(128) void kk_kernel()
{
    int idx = blockIdx.x * 128 + threadIdx.x;
    int t = idx >> 5, b = idx & 31;
    const float4* p0 = (const float4*)(g_proj + (size_t)(t * 32 + b) * 256);
    int t1 = (t + 1 < T_STEPS) ? t + 1 : t;
    int t2 = (t + 2 < T_STEPS) ? t + 2 : t;
    int t3 = (t + 3 < T_STEPS) ? t + 3 : t;
    const float4* p1 = (const float4*)(g_proj + (size_t)(t1 * 32 + b) * 256);
    const float4* p2 = (const float4*)(g_proj + (size_t)(t2 * 32 + b) * 256);
    const float4* p3 = (const float4*)(g_proj + (size_t)(t3 * 32 + b) * 256);
    float a1 = 0.f, a2 = 0.f, a3 = 0.f;
    #pragma unroll
    for (int i = 0; i < 16; i++) {
        float4 k0 = p0[i], q1 = p1[i], q2 = p2[i], q3 = p3[i];
        a1 += k0.x*q1.x + k0.y*q1.y + k0.z*q1.z + k0.w*q1.w;
        a2 += k0.x*q2.x + k0.y*q2.y + k0.z*q2.z + k0.w*q2.w;
        a3 += k0.x*q3.x + k0.y*q3.y + k0.z*q3.z + k0.w*q3.w;
    }
    if (t + 1 >= T_STEPS) a1 = 0.f;
    if (t + 2 >= T_STEPS) a2 = 0.f;
    if (t + 3 >= T_STEPS) a3 = 0.f;
    g_kk[idx] = make_float4(a1, a2, a3, 0.f);
}

// ---------------------------------------------------------------------------
// Scan v5: sigma-affine recurrence + warp-private cp.async block staging.
// 128 CTAs x 128 thr; warp = 4 rows x 8 lanes. Per 8-step block each warp
// stages k (3-deep ring, t+4 dot crosses blocks), q, and scalars (2-deep,
// axb pre-shifted +1) into its own smem; steady-state steps are LDS-only.
// Per-warp float layout (2752 floats = 11008 B):
//   K ring:  [0,1536)   3 x 512   (8 steps x 64 floats)
//   Q ring:  [1536,2560) 2 x 512
//   SC ring: [2560,2752) 2 x 96   (v[8x4] | ax_{t+1}[8x4] | kk[8x4])
// ---------------------------------------------------------------------------
__global__ __launch_bounds__(128) void scan_kernel(
    const float* __restrict__ S_in,
    const float* __restrict__ d_alpha,
    const float* __restrict__ b_alpha,
    float* __restrict__ out)
{
    __shared__ __align__(16) float sm4[4][2752];

    const int tid  = threadIdx.x;
    const int w    = tid >> 5;
    const int lane = tid & 31;
    const int rl   = tid >> 3;       // 0..15
    const int g    = tid & 7;        // lane slice within row
    const int wr4  = rl & 3;         // row within warp
    const int b    = blockIdx.x >> 2;
    const int rg   = blockIdx.x & 3;
    const int row  = rg * 16 + rl;
    const int c0   = g * 8;

    float* wsm = sm4[w];
    const uint32_t wsb = smem_u32(wsm);

    auto issue = [&](int B, bool doK, bool doQ, bool doS) {
        if (doK) {
            int ks = (B + 2) % 3;
            int tb = (B + 2) * 8;
            uint32_t dst = wsb + ks * 2048;
            #pragma unroll
            for (int i = 0; i < 4; i++) {
                int c = lane + 32 * i;           // 0..127 (16B chunks)
                int t = c >> 4;
                int gt = tb + t; if (gt > 511) gt = 511;
                cp16(dst + c * 16, g_proj + ((size_t)(gt * 32 + b)) * 256 + (c & 15) * 4);
            }
        }
        if (doQ) {
            int qs = (B + 1) & 1;
            int tb = (B + 1) * 8;
            uint32_t dst = wsb + 6144 + qs * 2048;
            #pragma unroll
            for (int i = 0; i < 4; i++) {
                int c = lane + 32 * i;
                int t = c >> 4;
                int gt = tb + t; if (gt > 511) gt = 511;
                cp16(dst + c * 16, g_proj + ((size_t)(gt * 32 + b)) * 256 + 64 + (c & 15) * 4);
            }
        }
        if (doS) {
            int ss = (B + 1) & 1;
            int tb = (B + 1) * 8;
            uint32_t dst = wsb + 10240 + ss * 384;
            if (lane < 8) {                       // v[t], warp's 4 rows
                int gt = tb + lane; if (gt > 511) gt = 511;
                cp16(dst + lane * 16,
                     g_proj + ((size_t)(gt * 32 + b)) * 256 + 128 + rg * 16 + w * 4);
            } else if (lane < 16) {               // ax[t+1]
                int gt = tb + (lane - 8) + 1; if (gt > 511) gt = 511;
                cp16(dst + 128 + (lane - 8) * 16,
                     g_proj + ((size_t)(gt * 32 + b)) * 256 + 192 + rg * 16 + w * 4);
            } else if (lane < 24) {               // kk[t]
                int gt = tb + (lane - 16); if (gt > 511) gt = 511;
                cp16(dst + 256 + (lane - 16) * 16, (const float*)&g_kk[gt * 32 + b]);
            }
        }
        asm volatile("cp.async.commit_group;" ::: "memory");
    };

    // Prologue staging: k(0); then k(1)+q(0)+scal(0)
    issue(-2, true, false, false);
    issue(-1, true, true,  true);

    float S[8];
    {
        const float* sp = S_in + ((size_t)b * NS + row) * NS + c0;
        #pragma unroll
        for (int j = 0; j < 8; j++) S[j] = sp[j];
    }
    const float da = d_alpha[row];
    const float ba = b_alpha[row];
    const float axb0 = g_proj[(size_t)(0 * 32 + b) * 256 + 192 + row] + ba;

    auto red8 = [](float v) {
        v += __shfl_xor_sync(0xffffffffu, v, 1);
        v += __shfl_xor_sync(0xffffffffu, v, 2);
        v += __shfl_xor_sync(0xffffffffu, v, 4);
        return v;
    };

    float x, A1, A2, A3;
    float* outp = out + (size_t)b * NS + row;
    int ks = 0;   // k ring slot of current block

    for (int B = 0; B < 64; B++) {
        __syncwarp();
        issue(B, true, true, true);               // k(B+2), q(B+1), scal(B+1)
        asm volatile("cp.async.wait_group 1;" ::: "memory");
        __syncwarp();                             // k(B),k(B+1),q(B),scal(B) ready

        const int ks1 = (ks == 2) ? 0 : ks + 1;
        const float* kb  = wsm + ks * 512;
        const float* kb1 = wsm + ks1 * 512;
        const float* qb  = wsm + 1536 + (B & 1) * 512;
        const float* scb = wsm + 2560 + (B & 1) * 96;

        if (B == 0) {
            // initial x, A1..A3 vs S_init using k_0..k_3 (from k(0) buffer)
            float t0 = 0.f, t1 = 0.f, t2 = 0.f, t3 = 0.f;
            #pragma unroll
            for (int j = 0; j < 8; j++) {
                t0 = fmaf(S[j], kb[0 * 64 + c0 + j], t0);
                t1 = fmaf(S[j], kb[1 * 64 + c0 + j], t1);
                t2 = fmaf(S[j], kb[2 * 64 + c0 + j], t2);
                t3 = fmaf(S[j], kb[3 * 64 + c0 + j], t3);
            }
            float r0 = red8(t0);
            A1 = red8(t1); A2 = red8(t2); A3 = red8(t3);
            x = fmaf(da, r0, axb0);
        }

        #pragma unroll
        for (int t = 0; t < 8; t++) {
            // ---- LDS reads for this step ----
            const float* kt  = kb + t * 64 + c0;
            const float* k4t = ((t >= 4) ? kb1 : kb) + ((t + 4) & 7) * 64 + c0;
            const float* qt  = qb + t * 64 + c0;
            float4 ka = *(const float4*)kt,  kbv = *(const float4*)(kt + 4);
            float4 qa = *(const float4*)qt,  qbv = *(const float4*)(qt + 4);
            float4 ea = *(const float4*)k4t, ebv = *(const float4*)(k4t + 4);
            float kc[8]  = {ka.x, ka.y, ka.z, ka.w, kbv.x, kbv.y, kbv.z, kbv.w};
            float qc[8]  = {qa.x, qa.y, qa.z, qa.w, qbv.x, qbv.y, qbv.z, qbv.w};
            float k4c[8] = {ea.x, ea.y, ea.z, ea.w, ebv.x, ebv.y, ebv.z, ebv.w};
            const float vc  = scb[t * 4 + wr4];
            const float axn = scb[32 + t * 4 + wr4] + ba;    // ax_{t+1}
            float4 kk = *(const float4*)&scb[64 + t * 4];

            // ---- pre-sigma (independent of sg) ----
            float vk1 = vc * kk.x, vk2 = vc * kk.y, vk3 = vc * kk.z;
            float uA1 = A1 - vk1, uA2 = A2 - vk2, uA3 = A3 - vk3;
            float px  = da * uA1;
            float qx  = fmaf(da, vk1, axn);
            float tj[8], uj[8];
            #pragma unroll
            for (int j = 0; j < 8; j++) { tj[j] = vc * kc[j]; uj[j] = S[j] - tj[j]; }

            // ---- critical chain: sigmoid -> 1 FMA ----
            float sg = __fdividef(1.f, 1.f + __expf(-x));
            x = fmaf(sg, px, qx);

            // ---- sigma-affine updates ----
            A1 = fmaf(sg, uA2, vk2);
            A2 = fmaf(sg, uA3, vk3);
            float h0 = 0.f, h1 = 0.f, d0 = 0.f, d1 = 0.f;
            #pragma unroll
            for (int j = 0; j < 8; j++) {
                float s = fmaf(sg, uj[j], tj[j]);
                S[j] = s;
                if (j & 1) { h1 = fmaf(s, qc[j], h1); d1 = fmaf(s, k4c[j], d1); }
                else       { h0 = fmaf(s, qc[j], h0); d0 = fmaf(s, k4c[j], d0); }
            }
            float h = h0 + h1, d = d0 + d1;
            h += __shfl_xor_sync(0xffffffffu, h, 1); d += __shfl_xor_sync(0xffffffffu, d, 1);
            h += __shfl_xor_sync(0xffffffffu, h, 2); d += __shfl_xor_sync(0xffffffffu, d, 2);
            h += __shfl_xor_sync(0xffffffffu, h, 4); d += __shfl_xor_sync(0xffffffffu, d, 4);
            A3 = d;                                 // S_t . k_{t+4}

            if (g == 0) {
                float sh = __fdividef(1.f, 1.f + __expf(-h));
                outp[0] = h * h * sh;               // h * silu(h)
            }
            outp += BATCH * NS;
        }

        ks = ks1;
    }

    // S_final
    float* sf = out + (size_t)T_STEPS * BATCH * NS + ((size_t)b * NS + row) * NS + c0;
    #pragma unroll
    for (int j = 0; j < 8; j++) sf[j] = S[j];
}

// ---------------------------------------------------------------------------
extern "C" void kernel_launch(void* const* d_in, const int* in_sizes, int n_in,
                              void* d_out, int out_size) {
    const float* x  = (const float*)d_in[0];
    const float* S  = (const float*)d_in[1];
    const float* Wk = (const float*)d_in[2];
    const float* Wv = (const float*)d_in[3];
    const float* Wq = (const float*)d_in[4];
    const float* Wa = (const float*)d_in[5];
    const float* da = (const float*)d_in[6];
    const float* ba = (const float*)d_in[7];
    float* out = (float*)d_out;

    cudaFuncSetAttribute(proj_gemm_mma, cudaFuncAttributeMaxDynamicSharedMemorySize, GEMM_SMEM);

    prep_w<<<256, 256>>>(Wk, Wq, Wv, Wa);
    proj_gemm_mma<<<M_TOT / 128, 512, GEMM_SMEM>>>(x);
    kk_kernel<<<M_TOT / 128, 128>>>();
    scan_kernel<<<BATCH * 4, 128>>>(S, da, ba, out);
}

// round 13
// speedup vs baseline: 1.5410x; 1.5410x over previous
#include <cuda_runtime.h>
#include <cuda_bf16.h>
#include <cstdint>

#define T_STEPS 512
#define BATCH   32
#define DIM     1024
#define NS      64
#define M_TOT   (T_STEPS * BATCH)   // 16384

// ---------------------------------------------------------------------------
// Device scratch
// ---------------------------------------------------------------------------
__device__ __align__(16) float  g_proj[(size_t)M_TOT * 256];   // [m][{k,q,v,ax}x64]
__device__ __align__(16) float4 g_kk[M_TOT];
__device__ __align__(16) __nv_bfloat16 g_Wh[256 * DIM];        // rows: k,q,v,ax
__device__ __align__(16) __nv_bfloat16 g_Wl[256 * DIM];

// ---------------------------------------------------------------------------
// helpers
// ---------------------------------------------------------------------------
__device__ __forceinline__ uint32_t smem_u32(const void* p) {
    uint32_t a;
    asm("{ .reg .u64 t; cvta.to.shared.u64 t, %1; cvt.u32.u64 %0, t; }" : "=r"(a) : "l"(p));
    return a;
}
__device__ __forceinline__ uint32_t bfpack(float hi_elem, float lo_elem) {
    uint32_t r;
    asm("cvt.rn.bf16x2.f32 %0, %1, %2;" : "=r"(r) : "f"(hi_elem), "f"(lo_elem));
    return r;
}
__device__ __forceinline__ uint32_t swoff(int row, int unit) {
    return (uint32_t)(row * 64 + ((unit ^ ((row >> 1) & 3)) << 4));
}
__device__ __forceinline__ void cp16(uint32_t dst, const void* src) {
    asm volatile("cp.async.cg.shared.global [%0], [%1], 16;" :: "r"(dst), "l"(src) : "memory");
}
__device__ __forceinline__ void ldsm4(uint32_t* r, uint32_t a) {
    asm volatile("ldmatrix.sync.aligned.m8n8.x4.shared.b16 {%0,%1,%2,%3}, [%4];"
                 : "=r"(r[0]), "=r"(r[1]), "=r"(r[2]), "=r"(r[3]) : "r"(a));
}
__device__ __forceinline__ void ldsm2(uint32_t* r, uint32_t a) {
    asm volatile("ldmatrix.sync.aligned.m8n8.x2.shared.b16 {%0,%1}, [%2];"
                 : "=r"(r[0]), "=r"(r[1]) : "r"(a));
}
__device__ __forceinline__ void mma16816(float* c, const uint32_t* a, const uint32_t* b) {
    asm volatile(
        "mma.sync.aligned.m16n8k16.row.col.f32.bf16.bf16.f32 "
        "{%0,%1,%2,%3}, {%4,%5,%6,%7}, {%8,%9}, {%0,%1,%2,%3};"
        : "+f"(c[0]), "+f"(c[1]), "+f"(c[2]), "+f"(c[3])
        : "r"(a[0]), "r"(a[1]), "r"(a[2]), "r"(a[3]), "r"(b[0]), "r"(b[1]));
}

// ---------------------------------------------------------------------------
// Weight prep: split 4x[64,1024] fp32 into bf16 hi/lo, row order k,q,v,ax
// ---------------------------------------------------------------------------
__global__ __launch_bounds__(256) void prep_w(
    const float* __restrict__ Wk, const float* __restrict__ Wq,
    const float* __restrict__ Wv, const float* __restrict__ Wa)
{
    int idx = blockIdx.x * 256 + threadIdx.x;
    int r = idx >> 8, c4 = idx & 255;
    const float* W = (r < 64) ? Wk : (r < 128) ? Wq : (r < 192) ? Wv : Wa;
    float4 v = ((const float4*)(W + (size_t)(r & 63) * DIM))[c4];
    uint32_t h01 = bfpack(v.y, v.x);
    uint32_t h23 = bfpack(v.w, v.z);
    float l0 = v.x - __uint_as_float(h01 << 16);
    float l1 = v.y - __uint_as_float(h01 & 0xffff0000u);
    float l2 = v.z - __uint_as_float(h23 << 16);
    float l3 = v.w - __uint_as_float(h23 & 0xffff0000u);
    ((uint2*)g_Wh)[idx] = make_uint2(h01, h23);
    ((uint2*)g_Wl)[idx] = make_uint2(bfpack(l1, l0), bfpack(l3, l2));
}

// ---------------------------------------------------------------------------
// Tensor-core projection GEMM (mma.sync bf16x3) — unchanged (R7, passed)
// ---------------------------------------------------------------------------
#define STAGE_BYTES 49152
#define GEMM_SMEM   (2 * STAGE_BYTES)

__global__ __launch_bounds__(512) void proj_gemm_mma(const float* __restrict__ X)
{
    extern __shared__ char sm[];
    const uint32_t sb = smem_u32(sm);
    const int tid  = threadIdx.x;
    const int lane = tid & 31;
    const int wid  = tid >> 5;
    const int wm   = wid & 3;
    const int wn   = wid >> 2;
    const int m0   = blockIdx.x * 128;

    float c[2][8][4];
    #pragma unroll
    for (int i = 0; i < 2; i++)
        #pragma unroll
        for (int j = 0; j < 8; j++)
            #pragma unroll
            for (int q = 0; q < 4; q++) c[i][j][q] = 0.f;

    const int xrow = tid >> 2, xu = tid & 3;
    const int wp   = tid >> 8, wrow = tid & 255;

    auto issueW = [&](int ch, int s) {
        const __nv_bfloat16* src = (wp ? g_Wl : g_Wh) + (size_t)wrow * DIM + ch * 32;
        uint32_t dbase = sb + s * STAGE_BYTES + 16384 + wp * 16384;
        #pragma unroll
        for (int u = 0; u < 4; u++) cp16(dbase + swoff(wrow, u), src + u * 8);
        asm volatile("cp.async.commit_group;" ::: "memory");
    };
    float4 xa, xb;
    auto loadX = [&](int ch) {
        const float* p = X + (size_t)(m0 + xrow) * DIM + ch * 32 + xu * 8;
        xa = *(const float4*)p;
        xb = *(const float4*)(p + 4);
    };
    auto stsX = [&](int s) {
        uint32_t h01 = bfpack(xa.y, xa.x), h23 = bfpack(xa.w, xa.z);
        uint32_t h45 = bfpack(xb.y, xb.x), h67 = bfpack(xb.w, xb.z);
        float l0 = xa.x - __uint_as_float(h01 << 16);
        float l1 = xa.y - __uint_as_float(h01 & 0xffff0000u);
        float l2 = xa.z - __uint_as_float(h23 << 16);
        float l3 = xa.w - __uint_as_float(h23 & 0xffff0000u);
        float l4 = xb.x - __uint_as_float(h45 << 16);
        float l5 = xb.y - __uint_as_float(h45 & 0xffff0000u);
        float l6 = xb.z - __uint_as_float(h67 << 16);
        float l7 = xb.w - __uint_as_float(h67 & 0xffff0000u);
        uint32_t off = s * STAGE_BYTES + swoff(xrow, xu);
        *(uint4*)(sm + off)        = make_uint4(h01, h23, h45, h67);
        *(uint4*)(sm + off + 8192) = make_uint4(bfpack(l1, l0), bfpack(l3, l2),
                                                bfpack(l5, l4), bfpack(l7, l6));
    };

    issueW(0, 0);
    loadX(0);

    for (int ch = 0; ch < 32; ch++) {
        const int s = ch & 1;
        asm volatile("cp.async.wait_group 0;" ::: "memory");
        stsX(s);
        if (ch + 1 < 32) { issueW(ch + 1, s ^ 1); loadX(ch + 1); }
        __syncthreads();

        const uint32_t st = sb + s * STAGE_BYTES;
        #pragma unroll
        for (int kt = 0; kt < 2; kt++) {
            uint32_t ah[2][4], al[2][4];
            #pragma unroll
            for (int mt = 0; mt < 2; mt++) {
                uint32_t aoff = swoff(wm * 32 + mt * 16 + (lane & 15), kt * 2 + (lane >> 4));
                ldsm4(ah[mt], st + aoff);
                ldsm4(al[mt], st + 8192 + aoff);
            }
            #pragma unroll
            for (int nt = 0; nt < 8; nt++) {
                uint32_t boff = swoff(wn * 64 + nt * 8 + (lane & 7),
                                      kt * 2 + ((lane >> 3) & 1));
                uint32_t bh[2], bl[2];
                ldsm2(bh, st + 16384 + boff);
                ldsm2(bl, st + 32768 + boff);
                mma16816(c[0][nt], ah[0], bh);
                mma16816(c[1][nt], ah[1], bh);
                mma16816(c[0][nt], al[0], bh);
                mma16816(c[1][nt], al[1], bh);
                mma16816(c[0][nt], ah[0], bl);
                mma16816(c[1][nt], ah[1], bl);
            }
        }
        __syncthreads();
    }

    #pragma unroll
    for (int mt = 0; mt < 2; mt++) {
        #pragma unroll
        for (int nt = 0; nt < 8; nt++) {
            int m = m0 + wm * 32 + mt * 16 + (lane >> 2);
            int n = wn * 64 + nt * 8 + (lane & 3) * 2;
            *(float2*)&g_proj[(size_t)m * 256 + n]       = make_float2(c[mt][nt][0], c[mt][nt][1]);
            *(float2*)&g_proj[(size_t)(m + 8) * 256 + n] = make_float2(c[mt][nt][2], c[mt][nt][3]);
        }
    }
}

// ---------------------------------------------------------------------------
// kk kernel: g_kk[t][b] = {k_t·k_{t+1}, k_t·k_{t+2}, k_t·k_{t+3}, 0}
// ---------------------------------------------------------------------------
__global__ __launch_bounds__(128) void kk_kernel()
{
    int idx = blockIdx.x * 128 + threadIdx.x;
    int t = idx >> 5, b = idx & 31;
    const float4* p0 = (const float4*)(g_proj + (size_t)(t * 32 + b) * 256);
    int t1 = (t + 1 < T_STEPS) ? t + 1 : t;
    int t2 = (t + 2 < T_STEPS) ? t + 2 : t;
    int t3 = (t + 3 < T_STEPS) ? t + 3 : t;
    const float4* p1 = (const float4*)(g_proj + (size_t)(t1 * 32 + b) * 256);
    const float4* p2 = (const float4*)(g_proj + (size_t)(t2 * 32 + b) * 256);
    const float4* p3 = (const float4*)(g_proj + (size_t)(t3 * 32 + b) * 256);
    float a1 = 0.f, a2 = 0.f, a3 = 0.f;
    #pragma unroll
    for (int i = 0; i < 16; i++) {
        float4 k0 = p0[i], q1 = p1[i], q2 = p2[i], q3 = p3[i];
        a1 += k0.x*q1.x + k0.y*q1.y + k0.z*q1.z + k0.w*q1.w;
        a2 += k0.x*q2.x + k0.y*q2.y + k0.z*q2.z + k0.w*q2.w;
        a3 += k0.x*q3.x + k0.y*q3.y + k0.z*q3.z + k0.w*q3.w;
    }
    if (t + 1 >= T_STEPS) a1 = 0.f;
    if (t + 2 >= T_STEPS) a2 = 0.f;
    if (t + 3 >= T_STEPS) a3 = 0.f;
    g_kk[idx] = make_float4(a1, a2, a3, 0.f);
}

// ---------------------------------------------------------------------------
// Scan v6: sigma-affine recurrence, 16 lanes/row (4 cols each), warp = 2 rows,
// CTA = 8 rows of one batch. Grid 256 CTAs x 128 thr -> 1024 warps
// (~2 warps/SMSP) so independent chains fill each other's stall cycles.
// k/q/kk staged ONCE per CTA via cp.async (shared by all rows); v/ax per-row.
// Steady state is LDS-only. Two __syncthreads per 8-step block.
// smem float layout (2880 floats):
//   k:  [0,1536)    3 x 512  (8 steps x 64)
//   q:  [1536,2560) 2 x 512
//   kk: [2560,2624) 2 x 32   (8 x float4)
//   v:  [2624,2752) 2 x 64   (8 steps x 8 rows)
//   ax: [2752,2880) 2 x 64   (pre-shifted +1)
// ---------------------------------------------------------------------------
__global__ __launch_bounds__(128) void scan_kernel(
    const float* __restrict__ S_in,
    const float* __restrict__ d_alpha,
    const float* __restrict__ b_alpha,
    float* __restrict__ out)
{
    __shared__ __align__(16) float sms[2880];

    const int tid  = threadIdx.x;
    const int w    = tid >> 5;
    const int lane = tid & 31;
    const int half = lane >> 4;      // which of the warp's 2 rows
    const int sub  = lane & 15;      // lane within row
    const int b    = blockIdx.x >> 3;
    const int rg   = blockIdx.x & 7; // 8 CTAs per batch
    const int r0   = rg * 8;
    const int wr   = w * 2 + half;   // row within CTA (0..7)
    const int row  = r0 + wr;
    const int c0   = sub * 4;

    const uint32_t smb = smem_u32(sms);

    auto issue = [&](int B) {
        {   // k(B+2) -> slot (B+2)%3 ; 128 cp16, one per thread
            int ks = (B + 2) % 3;
            int tb = (B + 2) * 8;
            int t = tid >> 4, u = tid & 15;
            int gt = tb + t; if (gt > 511) gt = 511;
            cp16(smb + (uint32_t)(ks * 512 + t * 64 + u * 4) * 4,
                 g_proj + ((size_t)(gt * 32 + b)) * 256 + u * 4);
        }
        if (B >= -1) {
            int ss = (B + 1) & 1;
            int tb = (B + 1) * 8;
            {   // q(B+1) ; 128 cp16
                int t = tid >> 4, u = tid & 15;
                int gt = tb + t; if (gt > 511) gt = 511;
                cp16(smb + (uint32_t)(1536 + ss * 512 + t * 64 + u * 4) * 4,
                     g_proj + ((size_t)(gt * 32 + b)) * 256 + 64 + u * 4);
            }
            if (tid < 8) {          // kk(B+1)
                int gt = tb + tid; if (gt > 511) gt = 511;
                cp16(smb + (uint32_t)(2560 + ss * 32 + tid * 4) * 4,
                     (const float*)&g_kk[gt * 32 + b]);
            } else if (tid < 24) {  // v(B+1), CTA's 8 rows
                int i = tid - 8, t = i >> 1, hf = i & 1;
                int gt = tb + t; if (gt > 511) gt = 511;
                cp16(smb + (uint32_t)(2624 + ss * 64 + t * 8 + hf * 4) * 4,
                     g_proj + ((size_t)(gt * 32 + b)) * 256 + 128 + r0 + hf * 4);
            } else if (tid < 40) {  // ax(B+1) shifted +1
                int i = tid - 24, t = i >> 1, hf = i & 1;
                int gt = tb + t + 1; if (gt > 511) gt = 511;
                cp16(smb + (uint32_t)(2752 + ss * 64 + t * 8 + hf * 4) * 4,
                     g_proj + ((size_t)(gt * 32 + b)) * 256 + 192 + r0 + hf * 4);
            }
        }
        asm volatile("cp.async.commit_group;" ::: "memory");
    };

    issue(-2);   // k(0)
    issue(-1);   // k(1) + q(0) + scal(0)

    float S[4];
    {
        const float* sp = S_in + ((size_t)b * NS + row) * NS + c0;
        #pragma unroll
        for (int j = 0; j < 4; j++) S[j] = sp[j];
    }
    const float da = d_alpha[row];
    const float ba = b_alpha[row];
    const float axb0 = g_proj[(size_t)b * 256 + 192 + row] + ba;   // t=0

    auto red16 = [](float v) {
        v += __shfl_xor_sync(0xffffffffu, v, 1);
        v += __shfl_xor_sync(0xffffffffu, v, 2);
        v += __shfl_xor_sync(0xffffffffu, v, 4);
        v += __shfl_xor_sync(0xffffffffu, v, 8);
        return v;
    };

    float x, A1, A2, A3;
    float* outp = out + (size_t)b * NS + row;

    for (int B = 0; B < 64; B++) {
        __syncthreads();                                   // consumers done with slot (B+2)%3
        issue(B);                                          // k(B+2), q(B+1), scal(B+1)
        asm volatile("cp.async.wait_group 1;" ::: "memory");
        __syncthreads();                                   // k(B),k(B+1),q(B),scal(B) visible

        const int ck = B % 3, nk = (B + 1) % 3;
        const float* kb  = sms + ck * 512;
        const float* kbn = sms + nk * 512;
        const float* qb  = sms + 1536 + (B & 1) * 512;
        const float* kkb = sms + 2560 + (B & 1) * 32;
        const float* vb  = sms + 2624 + (B & 1) * 64;
        const float* axv = sms + 2752 + (B & 1) * 64;

        if (B == 0) {
            float t0 = 0.f, t1 = 0.f, t2 = 0.f, t3 = 0.f;
            #pragma unroll
            for (int j = 0; j < 4; j++) {
                t0 = fmaf(S[j], kb[0 * 64 + c0 + j], t0);
                t1 = fmaf(S[j], kb[1 * 64 + c0 + j], t1);
                t2 = fmaf(S[j], kb[2 * 64 + c0 + j], t2);
                t3 = fmaf(S[j], kb[3 * 64 + c0 + j], t3);
            }
            float r0v = red16(t0);
            A1 = red16(t1); A2 = red16(t2); A3 = red16(t3);
            x = fmaf(da, r0v, axb0);
        }

        #pragma unroll
        for (int t = 0; t < 8; t++) {
            // ---- LDS reads ----
            float4 kv = *(const float4*)(kb + t * 64 + c0);
            float4 qv = *(const float4*)(qb + t * 64 + c0);
            float4 k4 = *(const float4*)(((t < 4) ? kb + (t + 4) * 64
                                                  : kbn + (t - 4) * 64) + c0);
            const float vc  = vb[t * 8 + wr];
            const float axn = axv[t * 8 + wr] + ba;        // ax_{t+1}
            float4 kk = *(const float4*)(kkb + t * 4);

            // ---- pre-sigma (independent of sg) ----
            float vk1 = vc * kk.x, vk2 = vc * kk.y, vk3 = vc * kk.z;
            float uA1 = A1 - vk1, uA2 = A2 - vk2, uA3 = A3 - vk3;
            float px  = da * uA1;
            float qx  = fmaf(da, vk1, axn);
            float tj0 = vc * kv.x, tj1 = vc * kv.y, tj2 = vc * kv.z, tj3 = vc * kv.w;
            float uj0 = S[0] - tj0, uj1 = S[1] - tj1, uj2 = S[2] - tj2, uj3 = S[3] - tj3;

            // ---- critical chain: sigmoid -> 1 FMA ----
            float sg = __fdividef(1.f, 1.f + __expf(-x));
            x = fmaf(sg, px, qx);

            // ---- sigma-affine updates ----
            A1 = fmaf(sg, uA2, vk2);
            A2 = fmaf(sg, uA3, vk3);
            float s0 = fmaf(sg, uj0, tj0); S[0] = s0;
            float s1 = fmaf(sg, uj1, tj1); S[1] = s1;
            float s2 = fmaf(sg, uj2, tj2); S[2] = s2;
            float s3 = fmaf(sg, uj3, tj3); S[3] = s3;
            float h0 = fmaf(s2, qv.z, s0 * qv.x), h1 = fmaf(s3, qv.w, s1 * qv.y);
            float d0 = fmaf(s2, k4.z, s0 * k4.x), d1 = fmaf(s3, k4.w, s1 * k4.y);
            float h = h0 + h1, d = d0 + d1;
            h += __shfl_xor_sync(0xffffffffu, h, 1); d += __shfl_xor_sync(0xffffffffu, d, 1);
            h += __shfl_xor_sync(0xffffffffu, h, 2); d += __shfl_xor_sync(0xffffffffu, d, 2);
            h += __shfl_xor_sync(0xffffffffu, h, 4); d += __shfl_xor_sync(0xffffffffu, d, 4);
            h += __shfl_xor_sync(0xffffffffu, h, 8); d += __shfl_xor_sync(0xffffffffu, d, 8);
            A3 = d;                                        // S_t . k_{t+4}

            if (sub == 0) {
                float sh = __fdividef(1.f, 1.f + __expf(-h));
                outp[0] = h * h * sh;                      // h * silu(h)
            }
            outp += BATCH * NS;
        }
    }

    // S_final
    float* sf = out + (size_t)T_STEPS * BATCH * NS + ((size_t)b * NS + row) * NS + c0;
    *(float4*)sf = make_float4(S[0], S[1], S[2], S[3]);
}

// ---------------------------------------------------------------------------
extern "C" void kernel_launch(void* const* d_in, const int* in_sizes, int n_in,
                              void* d_out, int out_size) {
    const float* x  = (const float*)d_in[0];
    const float* S  = (const float*)d_in[1];
    const float* Wk = (const float*)d_in[2];
    const float* Wv = (const float*)d_in[3];
    const float* Wq = (const float*)d_in[4];
    const float* Wa = (const float*)d_in[5];
    const float* da = (const float*)d_in[6];
    const float* ba = (const float*)d_in[7];
    float* out = (float*)d_out;

    cudaFuncSetAttribute(proj_gemm_mma, cudaFuncAttributeMaxDynamicSharedMemorySize, GEMM_SMEM);

    prep_w<<<256, 256>>>(Wk, Wq, Wv, Wa);
    proj_gemm_mma<<<M_TOT / 128, 512, GEMM_SMEM>>>(x);
    kk_kernel<<<M_TOT / 128, 128>>>();
    scan_kernel<<<BATCH * 8, 128>>>(S, da, ba, out);
}